// round 6
// baseline (speedup 1.0000x reference)
#include <cuda_runtime.h>
#include <cuda_fp16.h>
#include <math.h>

#define B 8
#define L1 384
#define L2 384
#define H 128
#define H2 256
#define H4 512

// ---- scratch (allocation-free: __device__ globals) ----
__device__ float d_xp[B * L1 * H];   // x @ Wup^T + b
__device__ float d_yp[B * L2 * H];   // y @ Wq^T + b + hidden_proj(=Wvp_b)
__device__ float d_s [B * L1 * L2];  // scores, then softmax alpha (in place)
__device__ float d_ct[B * L1 * H];   // attention context
__device__ float d_li[B * L1 * H2];  // gated lstm input
__device__ float d_gx[B * L1 * H4];  // input-side LSTM gates (incl. b_ih + b_hh)
// W_hh transposed + fp16: layout [kk][t], kk in 0..31 covers k=4kk..4kk+3,
// element = uint2{ half2(w[t][4kk],w[t][4kk+1]), half2(w[t][4kk+2],w[t][4kk+3]) }
__device__ uint2 d_wt[32 * H4];

__device__ __forceinline__ float tanh_fast(float x) {
    float y;
    asm("tanh.approx.f32 %0, %1;" : "=f"(y) : "f"(x));
    return y;
}

// accurate-enough smooth activations (EX2-based, no branches)
__device__ __forceinline__ float sigmoid_acc(float x) {
    x = fminf(fmaxf(x, -30.f), 30.f);
    return 1.f / (1.f + __expf(-x));
}
__device__ __forceinline__ float tanh_acc(float x) {
    x = fminf(fmaxf(x, -15.f), 15.f);
    float e = __expf(-2.f * x);
    return (1.f - e) / (1.f + e);
}

// ============================================================
// Kernel A: row projections. rows [0, B*L1) -> xp, rows [B*L1, +B*L2) -> yp
// ============================================================
__global__ void k_proj(const float* __restrict__ x, const float* __restrict__ y,
                       const float* __restrict__ Wup, const float* __restrict__ bup,
                       const float* __restrict__ Wq,  const float* __restrict__ bq,
                       const float* __restrict__ bvp)
{
    int row = blockIdx.x;
    int o   = threadIdx.x;
    __shared__ float4 in4[H / 4];

    const float* in;
    const float* W;
    float bias;
    float* out;
    if (row < B * L1) {
        in = x + (size_t)row * H;  W = Wup;  bias = bup[o];           out = d_xp + (size_t)row * H;
    } else {
        int r = row - B * L1;
        in = y + (size_t)r * H;    W = Wq;   bias = bq[o] + bvp[o];   out = d_yp + (size_t)r * H;
    }
    if (o < H / 4) in4[o] = ((const float4*)in)[o];
    __syncthreads();

    const float4* W4 = (const float4*)(W + (size_t)o * H);
    float acc = bias;
#pragma unroll
    for (int k = 0; k < H / 4; k++) {
        float4 w = W4[k];
        float4 v = in4[k];
        acc += w.x * v.x + w.y * v.y + w.z * v.z + w.w * v.w;
    }
    out[o] = acc;
}

// ============================================================
// Kernel A2: transpose + fp16-pack W_hh for the LSTM.
// idx = t*32 + kk  -> coalesced float4 read of W row t.
// ============================================================
__global__ void k_prep(const float* __restrict__ Whh)
{
    int idx = blockIdx.x * 512 + threadIdx.x;   // 0 .. 32*512-1
    int t  = idx >> 5;
    int kk = idx & 31;
    float4 w = ((const float4*)(Whh + (size_t)t * H))[kk];
    uint2 o;
    half2 lo = __floats2half2_rn(w.x, w.y);
    half2 hi = __floats2half2_rn(w.z, w.w);
    o.x = *(unsigned int*)&lo;
    o.y = *(unsigned int*)&hi;
    d_wt[kk * H4 + t] = o;
}

// ============================================================
// Kernel B: additive attention scores (MUFU-bound)
// ============================================================
__global__ void k_scores(const unsigned char* __restrict__ xmask,
                         const unsigned char* __restrict__ ymask,
                         const float* __restrict__ Vw, const float* __restrict__ Vb)
{
    int b  = blockIdx.z;
    int t0 = blockIdx.y * 32;
    int j0 = blockIdx.x * 32;

    __shared__ float4 xs[32 * 32];
    __shared__ float4 ys[32 * 33];
    __shared__ float4 vs[32];

    int tid = threadIdx.y * 32 + threadIdx.x;
    for (int i = tid; i < 32 * 32; i += 256) {
        int r = i >> 5, k = i & 31;
        xs[r * 32 + k] = ((const float4*)(d_xp + (size_t)((b * L1) + t0 + r) * H))[k];
        ys[r * 33 + k] = ((const float4*)(d_yp + (size_t)((b * L2) + j0 + r) * H))[k];
    }
    if (tid < 32) vs[tid] = ((const float4*)Vw)[tid];
    __syncthreads();

    int j = threadIdx.x;
    float acc[4] = {0.f, 0.f, 0.f, 0.f};

#pragma unroll 4
    for (int k = 0; k < 32; k++) {
        float4 yv = ys[j * 33 + k];
        float4 v  = vs[k];
#pragma unroll
        for (int i = 0; i < 4; i++) {
            float4 xv = xs[(threadIdx.y + i * 8) * 32 + k];
            acc[i] += v.x * tanh_fast(xv.x + yv.x);
            acc[i] += v.y * tanh_fast(xv.y + yv.y);
            acc[i] += v.z * tanh_fast(xv.z + yv.z);
            acc[i] += v.w * tanh_fast(xv.w + yv.w);
        }
    }

    bool  ymb = ymask[b * L2 + j0 + j] != 0;
    float ymv = ymb ? 0.f : 1.f;
    float vb  = Vb[0];
    const float NEG_INF = __int_as_float(0xff800000);
#pragma unroll
    for (int i = 0; i < 4; i++) {
        int t   = t0 + threadIdx.y + i * 8;
        float xm = (xmask[b * L1 + t] != 0) ? 0.f : 1.f;
        float s  = (acc[i] + vb) * (xm * ymv);
        if (ymb) s = NEG_INF;
        d_s[(size_t)((b * L1) + t) * L2 + j0 + j] = s;
    }
}

// ============================================================
// Kernel C: softmax over j. one block / row.
// ============================================================
__global__ void k_softmax()
{
    int row = blockIdx.x;
    float* s = d_s + (size_t)row * L2;
    int tid = threadIdx.x;   // 128

    float v[3];
    float m = -INFINITY;
#pragma unroll
    for (int i = 0; i < 3; i++) { v[i] = s[tid + i * 128]; m = fmaxf(m, v[i]); }

    __shared__ float red[4];
#pragma unroll
    for (int o = 16; o > 0; o >>= 1) m = fmaxf(m, __shfl_xor_sync(~0u, m, o));
    if ((tid & 31) == 0) red[tid >> 5] = m;
    __syncthreads();
    m = fmaxf(fmaxf(red[0], red[1]), fmaxf(red[2], red[3]));

    float sum = 0.f;
#pragma unroll
    for (int i = 0; i < 3; i++) { v[i] = __expf(v[i] - m); sum += v[i]; }
#pragma unroll
    for (int o = 16; o > 0; o >>= 1) sum += __shfl_xor_sync(~0u, sum, o);
    __shared__ float red2[4];
    if ((tid & 31) == 0) red2[tid >> 5] = sum;
    __syncthreads();
    sum = red2[0] + red2[1] + red2[2] + red2[3];

    float inv = 1.0f / sum;
#pragma unroll
    for (int i = 0; i < 3; i++) s[tid + i * 128] = v[i] * inv;
}

// ============================================================
// Kernel D: ct[b,t,:] = sum_j alpha[b,t,j] * y[b,j,:]
// 256 threads handle 16 t-rows; j in chunks of 32, register double-buffered.
// ============================================================
#define NCHUNK (L2 / 32)
__global__ void k_ctx(const float* __restrict__ y)
{
    int b  = blockIdx.y;
    int t0 = blockIdx.x * 16;
    __shared__ __align__(16) float ysm[32 * 128];
    __shared__ float alph[16 * 32];

    int tid = threadIdx.x;       // 256
    int h   = tid & 127;
    int tg  = tid >> 7;          // 0..1 -> owns 8 t's
    float acc[8] = {0.f, 0.f, 0.f, 0.f, 0.f, 0.f, 0.f, 0.f};

    const float4* y4 = (const float4*)(y + (size_t)b * L2 * H);
    const float*  sp = d_s + (size_t)(b * L1 + t0) * L2;

    float4 ybuf[4];
    float  abuf[2];
#pragma unroll
    for (int q = 0; q < 4; q++) ybuf[q] = y4[tid + 256 * q];
#pragma unroll
    for (int q = 0; q < 2; q++) {
        int i = tid + 256 * q;
        abuf[q] = sp[(size_t)(i >> 5) * L2 + (i & 31)];
    }

    for (int c = 0; c < NCHUNK; c++) {
        __syncthreads();
#pragma unroll
        for (int q = 0; q < 4; q++) ((float4*)ysm)[tid + 256 * q] = ybuf[q];
#pragma unroll
        for (int q = 0; q < 2; q++) alph[tid + 256 * q] = abuf[q];
        __syncthreads();

        if (c + 1 < NCHUNK) {
#pragma unroll
            for (int q = 0; q < 4; q++) ybuf[q] = y4[(c + 1) * 1024 + tid + 256 * q];
#pragma unroll
            for (int q = 0; q < 2; q++) {
                int i = tid + 256 * q;
                abuf[q] = sp[(size_t)(i >> 5) * L2 + (c + 1) * 32 + (i & 31)];
            }
        }

#pragma unroll 8
        for (int jj = 0; jj < 32; jj++) {
            float yv = ysm[jj * 128 + h];
#pragma unroll
            for (int i = 0; i < 8; i++)
                acc[i] += alph[(tg * 8 + i) * 32 + jj] * yv;
        }
    }
#pragma unroll
    for (int i = 0; i < 8; i++)
        d_ct[(size_t)((b * L1) + t0 + tg * 8 + i) * H + h] = acc[i];
}

// ============================================================
// Kernel E1: li = sigmoid([x,ct] @ Wg^T + bg) * [x,ct]
// ============================================================
__global__ void k_gate(const float* __restrict__ x,
                       const float* __restrict__ Wg, const float* __restrict__ bg)
{
    int r0 = blockIdx.x * 32;
    int c  = threadIdx.x;                         // 256 cols
    __shared__ __align__(16) float ms[32 * H2];

    for (int i = c; i < 32 * H2; i += 256) {
        int r = i >> 8, k = i & 255;
        ms[i] = (k < H) ? x[(size_t)(r0 + r) * H + k]
                        : d_ct[(size_t)(r0 + r) * H + (k - H)];
    }
    __syncthreads();

    float acc[32];
#pragma unroll
    for (int r = 0; r < 32; r++) acc[r] = 0.f;

    const float4* W4  = (const float4*)(Wg + (size_t)c * H2);
    const float4* ms4 = (const float4*)ms;
    for (int k = 0; k < H2 / 4; k++) {
        float4 w = W4[k];
#pragma unroll
        for (int r = 0; r < 32; r++) {
            float4 m = ms4[r * (H2 / 4) + k];
            acc[r] += w.x * m.x + w.y * m.y + w.z * m.z + w.w * m.w;
        }
    }
    float bias = bg[c];
#pragma unroll
    for (int r = 0; r < 32; r++) {
        float g = 1.0f / (1.0f + __expf(-(acc[r] + bias)));
        d_li[(size_t)(r0 + r) * H2 + c] = g * ms[r * H2 + c];
    }
}

// ============================================================
// Kernel E2: gx = li @ W_ih^T + (b_ih + b_hh)
// ============================================================
__global__ void k_gatesx(const float* __restrict__ Wih, const float* __restrict__ bih,
                         const float* __restrict__ bhh)
{
    int r0 = blockIdx.x * 32;
    int c0 = blockIdx.y * 256;
    int c  = c0 + threadIdx.x;
    __shared__ __align__(16) float ms[32 * H2];

    for (int i = threadIdx.x; i < 32 * H2; i += 256)
        ms[i] = d_li[(size_t)(r0 + (i >> 8)) * H2 + (i & 255)];
    __syncthreads();

    float acc[32];
#pragma unroll
    for (int r = 0; r < 32; r++) acc[r] = 0.f;

    const float4* W4  = (const float4*)(Wih + (size_t)c * H2);
    const float4* ms4 = (const float4*)ms;
    for (int k = 0; k < H2 / 4; k++) {
        float4 w = W4[k];
#pragma unroll
        for (int r = 0; r < 32; r++) {
            float4 m = ms4[r * (H2 / 4) + k];
            acc[r] += w.x * m.x + w.y * m.y + w.z * m.z + w.w * m.w;
        }
    }
    float bias = bih[c] + bhh[c];
#pragma unroll
    for (int r = 0; r < 32; r++)
        d_gx[(size_t)(r0 + r) * H4 + c] = acc[r] + bias;
}

// ============================================================
// Kernel F: LSTM scan. One block per batch, 512 threads = one gate each.
// W_hh lives in PER-THREAD REGISTERS as fp16 (32 x uint2 = 64 regs):
// zero W memory traffic per step; only broadcast LDS reads of h remain.
// fp32 accumulate; gx prefetched; EX2 activations.
// ============================================================
__global__ void __launch_bounds__(512, 1)
k_lstm(float* __restrict__ out)
{
    __shared__ __align__(16) float hs[H];
    __shared__ float gs[H4];

    int b = blockIdx.x;
    int t = threadIdx.x;                       // gate index 0..511

    // Load this gate's 128 fp16 weights into registers (one-time).
    // d_wt layout [kk][t]: consecutive t -> consecutive uint2 (coalesced).
    uint2 wreg[32];
#pragma unroll
    for (int kk = 0; kk < 32; kk++)
        wreg[kk] = d_wt[kk * H4 + t];

    if (t < H) hs[t] = 0.f;
    float c = 0.f;
    const float* __restrict__ gxp = d_gx + (size_t)b * L1 * H4 + t;
    bool is_tanh_gate = ((t >> 7) == 2);

    float gx = gxp[0];
    __syncthreads();
    const float4* h4 = (const float4*)hs;

    for (int step = 0; step < L1; step++) {
        float g = gx;
        if (step + 1 < L1)
            gx = gxp[(size_t)(step + 1) * H4];  // prefetch next step

        float a0 = 0.f, a1 = 0.f, a2 = 0.f, a3 = 0.f;
#pragma unroll
        for (int kk = 0; kk < 32; kk++) {
            float4 hv = h4[kk];                 // broadcast LDS.128
            float2 lo = __half22float2(*(const half2*)&wreg[kk].x);
            float2 hi = __half22float2(*(const half2*)&wreg[kk].y);
            a0 += lo.x * hv.x;
            a1 += lo.y * hv.y;
            a2 += hi.x * hv.z;
            a3 += hi.y * hv.w;
        }
        g += (a0 + a1) + (a2 + a3);

        gs[t] = is_tanh_gate ? tanh_acc(g) : sigmoid_acc(g);
        __syncthreads();

        if (t < H) {
            float gi = gs[t], gf = gs[t + H], gg = gs[t + 2 * H], go = gs[t + 3 * H];
            c = gf * c + gi * gg;
            float hn = go * tanh_acc(c);
            hs[t] = hn;
            out[(size_t)((b * L1) + step) * H + t] = hn;
        }
        __syncthreads();
    }
}

// ============================================================
extern "C" void kernel_launch(void* const* d_in, const int* in_sizes, int n_in,
                              void* d_out, int out_size)
{
    const float*         x     = (const float*)d_in[0];
    const unsigned char* xmask = (const unsigned char*)d_in[1];
    const float*         y     = (const float*)d_in[2];
    const unsigned char* ymask = (const unsigned char*)d_in[3];
    const float* Wq_w  = (const float*)d_in[4];
    const float* Wq_b  = (const float*)d_in[5];
    const float* Wup_w = (const float*)d_in[6];
    const float* Wup_b = (const float*)d_in[7];
    // d_in[8] = Wvp_w (multiplied by zeros in reference -> unused)
    const float* Wvp_b = (const float*)d_in[9];
    const float* V_w   = (const float*)d_in[10];
    const float* V_b   = (const float*)d_in[11];
    const float* Wg_w  = (const float*)d_in[12];
    const float* Wg_b  = (const float*)d_in[13];
    const float* W_ih  = (const float*)d_in[14];
    const float* W_hh  = (const float*)d_in[15];
    const float* b_ih  = (const float*)d_in[16];
    const float* b_hh  = (const float*)d_in[17];
    float* out = (float*)d_out;

    k_proj  <<<B * L1 + B * L2, 128>>>(x, y, Wup_w, Wup_b, Wq_w, Wq_b, Wvp_b);
    k_prep  <<<32, 512>>>(W_hh);
    k_scores<<<dim3(L2 / 32, L1 / 32, B), dim3(32, 8)>>>(xmask, ymask, V_w, V_b);
    k_softmax<<<B * L1, 128>>>();
    k_ctx   <<<dim3(L1 / 16, B), 256>>>(y);
    k_gate  <<<(B * L1) / 32, 256>>>(x, Wg_w, Wg_b);
    k_gatesx<<<dim3((B * L1) / 32, 2), 256>>>(W_ih, b_ih, b_hh);
    k_lstm  <<<B, 512>>>(out);
}

// round 7
// speedup vs baseline: 1.8441x; 1.8441x over previous
#include <cuda_runtime.h>
#include <cuda_fp16.h>
#include <math.h>

#define B 8
#define L1 384
#define L2 384
#define H 128
#define H2 256
#define H4 512

// ---- scratch (allocation-free: __device__ globals) ----
__device__ float d_xp[B * L1 * H];   // x @ Wup^T + b
__device__ float d_yp[B * L2 * H];   // y @ Wq^T + b + hidden_proj(=Wvp_b)
__device__ float d_s [B * L1 * L2];  // scores, then softmax alpha (in place)
__device__ float d_ct[B * L1 * H];   // attention context
__device__ float d_li[B * L1 * H2];  // gated lstm input
__device__ float d_gx[B * L1 * H4];  // input-side LSTM gates (incl. b_ih + b_hh)
// W_hh transposed + fp16: layout [kk][t], kk in 0..31 covers k=4kk..4kk+3,
// element = uint2{ half2(w[t][4kk],w[t][4kk+1]), half2(w[t][4kk+2],w[t][4kk+3]) }
__device__ uint2 d_wt[32 * H4];

__device__ __forceinline__ float tanh_fast(float x) {
    float y;
    asm("tanh.approx.f32 %0, %1;" : "=f"(y) : "f"(x));
    return y;
}

// accurate-enough smooth activations (EX2-based, no branches)
__device__ __forceinline__ float sigmoid_acc(float x) {
    x = fminf(fmaxf(x, -30.f), 30.f);
    return 1.f / (1.f + __expf(-x));
}
__device__ __forceinline__ float tanh_acc(float x) {
    x = fminf(fmaxf(x, -15.f), 15.f);
    float e = __expf(-2.f * x);
    return (1.f - e) / (1.f + e);
}

// ============================================================
// Kernel A: row projections. rows [0, B*L1) -> xp, rows [B*L1, +B*L2) -> yp
// ============================================================
__global__ void k_proj(const float* __restrict__ x, const float* __restrict__ y,
                       const float* __restrict__ Wup, const float* __restrict__ bup,
                       const float* __restrict__ Wq,  const float* __restrict__ bq,
                       const float* __restrict__ bvp)
{
    int row = blockIdx.x;
    int o   = threadIdx.x;
    __shared__ float4 in4[H / 4];

    const float* in;
    const float* W;
    float bias;
    float* out;
    if (row < B * L1) {
        in = x + (size_t)row * H;  W = Wup;  bias = bup[o];           out = d_xp + (size_t)row * H;
    } else {
        int r = row - B * L1;
        in = y + (size_t)r * H;    W = Wq;   bias = bq[o] + bvp[o];   out = d_yp + (size_t)r * H;
    }
    if (o < H / 4) in4[o] = ((const float4*)in)[o];
    __syncthreads();

    const float4* W4 = (const float4*)(W + (size_t)o * H);
    float acc = bias;
#pragma unroll
    for (int k = 0; k < H / 4; k++) {
        float4 w = W4[k];
        float4 v = in4[k];
        acc += w.x * v.x + w.y * v.y + w.z * v.z + w.w * v.w;
    }
    out[o] = acc;
}

// ============================================================
// Kernel A2: transpose + fp16-pack W_hh for the LSTM.
// ============================================================
__global__ void k_prep(const float* __restrict__ Whh)
{
    int idx = blockIdx.x * 512 + threadIdx.x;   // 0 .. 32*512-1
    int t  = idx >> 5;
    int kk = idx & 31;
    float4 w = ((const float4*)(Whh + (size_t)t * H))[kk];
    uint2 o;
    half2 lo = __floats2half2_rn(w.x, w.y);
    half2 hi = __floats2half2_rn(w.z, w.w);
    o.x = *(unsigned int*)&lo;
    o.y = *(unsigned int*)&hi;
    d_wt[kk * H4 + t] = o;
}

// ============================================================
// Kernel B: additive attention scores (MUFU-bound)
// ============================================================
__global__ void k_scores(const unsigned char* __restrict__ xmask,
                         const unsigned char* __restrict__ ymask,
                         const float* __restrict__ Vw, const float* __restrict__ Vb)
{
    int b  = blockIdx.z;
    int t0 = blockIdx.y * 32;
    int j0 = blockIdx.x * 32;

    __shared__ float4 xs[32 * 32];
    __shared__ float4 ys[32 * 33];
    __shared__ float4 vs[32];

    int tid = threadIdx.y * 32 + threadIdx.x;
    for (int i = tid; i < 32 * 32; i += 256) {
        int r = i >> 5, k = i & 31;
        xs[r * 32 + k] = ((const float4*)(d_xp + (size_t)((b * L1) + t0 + r) * H))[k];
        ys[r * 33 + k] = ((const float4*)(d_yp + (size_t)((b * L2) + j0 + r) * H))[k];
    }
    if (tid < 32) vs[tid] = ((const float4*)Vw)[tid];
    __syncthreads();

    int j = threadIdx.x;
    float acc[4] = {0.f, 0.f, 0.f, 0.f};

#pragma unroll 4
    for (int k = 0; k < 32; k++) {
        float4 yv = ys[j * 33 + k];
        float4 v  = vs[k];
#pragma unroll
        for (int i = 0; i < 4; i++) {
            float4 xv = xs[(threadIdx.y + i * 8) * 32 + k];
            acc[i] += v.x * tanh_fast(xv.x + yv.x);
            acc[i] += v.y * tanh_fast(xv.y + yv.y);
            acc[i] += v.z * tanh_fast(xv.z + yv.z);
            acc[i] += v.w * tanh_fast(xv.w + yv.w);
        }
    }

    bool  ymb = ymask[b * L2 + j0 + j] != 0;
    float ymv = ymb ? 0.f : 1.f;
    float vb  = Vb[0];
    const float NEG_INF = __int_as_float(0xff800000);
#pragma unroll
    for (int i = 0; i < 4; i++) {
        int t   = t0 + threadIdx.y + i * 8;
        float xm = (xmask[b * L1 + t] != 0) ? 0.f : 1.f;
        float s  = (acc[i] + vb) * (xm * ymv);
        if (ymb) s = NEG_INF;
        d_s[(size_t)((b * L1) + t) * L2 + j0 + j] = s;
    }
}

// ============================================================
// Kernel C: softmax over j. one block / row.
// ============================================================
__global__ void k_softmax()
{
    int row = blockIdx.x;
    float* s = d_s + (size_t)row * L2;
    int tid = threadIdx.x;   // 128

    float v[3];
    float m = -INFINITY;
#pragma unroll
    for (int i = 0; i < 3; i++) { v[i] = s[tid + i * 128]; m = fmaxf(m, v[i]); }

    __shared__ float red[4];
#pragma unroll
    for (int o = 16; o > 0; o >>= 1) m = fmaxf(m, __shfl_xor_sync(~0u, m, o));
    if ((tid & 31) == 0) red[tid >> 5] = m;
    __syncthreads();
    m = fmaxf(fmaxf(red[0], red[1]), fmaxf(red[2], red[3]));

    float sum = 0.f;
#pragma unroll
    for (int i = 0; i < 3; i++) { v[i] = __expf(v[i] - m); sum += v[i]; }
#pragma unroll
    for (int o = 16; o > 0; o >>= 1) sum += __shfl_xor_sync(~0u, sum, o);
    __shared__ float red2[4];
    if ((tid & 31) == 0) red2[tid >> 5] = sum;
    __syncthreads();
    sum = red2[0] + red2[1] + red2[2] + red2[3];

    float inv = 1.0f / sum;
#pragma unroll
    for (int i = 0; i < 3; i++) s[tid + i * 128] = v[i] * inv;
}

// ============================================================
// Kernel D: ct[b,t,:] = sum_j alpha[b,t,j] * y[b,j,:]
// ============================================================
#define NCHUNK (L2 / 32)
__global__ void k_ctx(const float* __restrict__ y)
{
    int b  = blockIdx.y;
    int t0 = blockIdx.x * 16;
    __shared__ __align__(16) float ysm[32 * 128];
    __shared__ float alph[16 * 32];

    int tid = threadIdx.x;       // 256
    int h   = tid & 127;
    int tg  = tid >> 7;
    float acc[8] = {0.f, 0.f, 0.f, 0.f, 0.f, 0.f, 0.f, 0.f};

    const float4* y4 = (const float4*)(y + (size_t)b * L2 * H);
    const float*  sp = d_s + (size_t)(b * L1 + t0) * L2;

    float4 ybuf[4];
    float  abuf[2];
#pragma unroll
    for (int q = 0; q < 4; q++) ybuf[q] = y4[tid + 256 * q];
#pragma unroll
    for (int q = 0; q < 2; q++) {
        int i = tid + 256 * q;
        abuf[q] = sp[(size_t)(i >> 5) * L2 + (i & 31)];
    }

    for (int c = 0; c < NCHUNK; c++) {
        __syncthreads();
#pragma unroll
        for (int q = 0; q < 4; q++) ((float4*)ysm)[tid + 256 * q] = ybuf[q];
#pragma unroll
        for (int q = 0; q < 2; q++) alph[tid + 256 * q] = abuf[q];
        __syncthreads();

        if (c + 1 < NCHUNK) {
#pragma unroll
            for (int q = 0; q < 4; q++) ybuf[q] = y4[(c + 1) * 1024 + tid + 256 * q];
#pragma unroll
            for (int q = 0; q < 2; q++) {
                int i = tid + 256 * q;
                abuf[q] = sp[(size_t)(i >> 5) * L2 + (c + 1) * 32 + (i & 31)];
            }
        }

#pragma unroll 8
        for (int jj = 0; jj < 32; jj++) {
            float yv = ysm[jj * 128 + h];
#pragma unroll
            for (int i = 0; i < 8; i++)
                acc[i] += alph[(tg * 8 + i) * 32 + jj] * yv;
        }
    }
#pragma unroll
    for (int i = 0; i < 8; i++)
        d_ct[(size_t)((b * L1) + t0 + tg * 8 + i) * H + h] = acc[i];
}

// ============================================================
// Kernel E1: li = sigmoid([x,ct] @ Wg^T + bg) * [x,ct]
// ============================================================
__global__ void k_gate(const float* __restrict__ x,
                       const float* __restrict__ Wg, const float* __restrict__ bg)
{
    int r0 = blockIdx.x * 32;
    int c  = threadIdx.x;                         // 256 cols
    __shared__ __align__(16) float ms[32 * H2];

    for (int i = c; i < 32 * H2; i += 256) {
        int r = i >> 8, k = i & 255;
        ms[i] = (k < H) ? x[(size_t)(r0 + r) * H + k]
                        : d_ct[(size_t)(r0 + r) * H + (k - H)];
    }
    __syncthreads();

    float acc[32];
#pragma unroll
    for (int r = 0; r < 32; r++) acc[r] = 0.f;

    const float4* W4  = (const float4*)(Wg + (size_t)c * H2);
    const float4* ms4 = (const float4*)ms;
    for (int k = 0; k < H2 / 4; k++) {
        float4 w = W4[k];
#pragma unroll
        for (int r = 0; r < 32; r++) {
            float4 m = ms4[r * (H2 / 4) + k];
            acc[r] += w.x * m.x + w.y * m.y + w.z * m.z + w.w * m.w;
        }
    }
    float bias = bg[c];
#pragma unroll
    for (int r = 0; r < 32; r++) {
        float g = 1.0f / (1.0f + __expf(-(acc[r] + bias)));
        d_li[(size_t)(r0 + r) * H2 + c] = g * ms[r * H2 + c];
    }
}

// ============================================================
// Kernel E2: gx = li @ W_ih^T + (b_ih + b_hh)
// ============================================================
__global__ void k_gatesx(const float* __restrict__ Wih, const float* __restrict__ bih,
                         const float* __restrict__ bhh)
{
    int r0 = blockIdx.x * 32;
    int c0 = blockIdx.y * 256;
    int c  = c0 + threadIdx.x;
    __shared__ __align__(16) float ms[32 * H2];

    for (int i = threadIdx.x; i < 32 * H2; i += 256)
        ms[i] = d_li[(size_t)(r0 + (i >> 8)) * H2 + (i & 255)];
    __syncthreads();

    float acc[32];
#pragma unroll
    for (int r = 0; r < 32; r++) acc[r] = 0.f;

    const float4* W4  = (const float4*)(Wih + (size_t)c * H2);
    const float4* ms4 = (const float4*)ms;
    for (int k = 0; k < H2 / 4; k++) {
        float4 w = W4[k];
#pragma unroll
        for (int r = 0; r < 32; r++) {
            float4 m = ms4[r * (H2 / 4) + k];
            acc[r] += w.x * m.x + w.y * m.y + w.z * m.z + w.w * m.w;
        }
    }
    float bias = bih[c] + bhh[c];
#pragma unroll
    for (int r = 0; r < 32; r++)
        d_gx[(size_t)(r0 + r) * H4 + c] = acc[r] + bias;
}

// ============================================================
// Kernel F: LSTM scan. One block per batch, 512 threads = one gate each.
// W_hh in registers as packed half2 (32 x uint2). h stored fp16 in SMEM.
// Dot product via HFMA2 (2 MACs/instr), accumulated in half2 over chunks
// of 8 products per lane, chunk sums promoted to fp32. c/gates/output fp32.
// Per-step floors: HFMA2 pipe ~512 cyc, issue ~540, crossbar ~512 wf.
// ============================================================
__global__ void __launch_bounds__(512, 1)
k_lstm(float* __restrict__ out)
{
    __shared__ __align__(8) __half hs[H];   // fp16 hidden state (256B)
    __shared__ float gs[H4];

    int b = blockIdx.x;
    int t = threadIdx.x;                    // gate index 0..511

    // One-time: this gate's 128 fp16 weights -> 32 uint2 registers.
    uint2 wreg[32];
#pragma unroll
    for (int kk = 0; kk < 32; kk++)
        wreg[kk] = d_wt[kk * H4 + t];

    if (t < H) hs[t] = __float2half_rn(0.f);
    float c = 0.f;
    const float* __restrict__ gxp = d_gx + (size_t)b * L1 * H4 + t;
    bool is_tanh_gate = ((t >> 7) == 2);

    float gx = gxp[0];
    __syncthreads();
    const uint2* h2p = (const uint2*)hs;    // 32 x (4 halves)

    for (int step = 0; step < L1; step++) {
        float g = gx;
        if (step + 1 < L1)
            gx = gxp[(size_t)(step + 1) * H4];   // prefetch next step

        float facc = 0.f;
#pragma unroll
        for (int ch = 0; ch < 4; ch++) {
            __half2 accA = __float2half2_rn(0.f);
            __half2 accB = __float2half2_rn(0.f);
#pragma unroll
            for (int q = 0; q < 8; q++) {
                int kk = ch * 8 + q;
                uint2 hv = h2p[kk];                   // broadcast LDS.64
                accA = __hfma2(*(const __half2*)&wreg[kk].x,
                               *(const __half2*)&hv.x, accA);
                accB = __hfma2(*(const __half2*)&wreg[kk].y,
                               *(const __half2*)&hv.y, accB);
            }
            float2 fa = __half22float2(accA);
            float2 fb = __half22float2(accB);
            facc += (fa.x + fa.y) + (fb.x + fb.y);
        }
        g += facc;

        gs[t] = is_tanh_gate ? tanh_acc(g) : sigmoid_acc(g);
        __syncthreads();

        if (t < H) {
            float gi = gs[t], gf = gs[t + H], gg = gs[t + 2 * H], go = gs[t + 3 * H];
            c = gf * c + gi * gg;
            float hn = go * tanh_acc(c);
            hs[t] = __float2half_rn(hn);
            out[(size_t)((b * L1) + step) * H + t] = hn;
        }
        __syncthreads();
    }
}

// ============================================================
extern "C" void kernel_launch(void* const* d_in, const int* in_sizes, int n_in,
                              void* d_out, int out_size)
{
    const float*         x     = (const float*)d_in[0];
    const unsigned char* xmask = (const unsigned char*)d_in[1];
    const float*         y     = (const float*)d_in[2];
    const unsigned char* ymask = (const unsigned char*)d_in[3];
    const float* Wq_w  = (const float*)d_in[4];
    const float* Wq_b  = (const float*)d_in[5];
    const float* Wup_w = (const float*)d_in[6];
    const float* Wup_b = (const float*)d_in[7];
    // d_in[8] = Wvp_w (multiplied by zeros in reference -> unused)
    const float* Wvp_b = (const float*)d_in[9];
    const float* V_w   = (const float*)d_in[10];
    const float* V_b   = (const float*)d_in[11];
    const float* Wg_w  = (const float*)d_in[12];
    const float* Wg_b  = (const float*)d_in[13];
    const float* W_ih  = (const float*)d_in[14];
    const float* W_hh  = (const float*)d_in[15];
    const float* b_ih  = (const float*)d_in[16];
    const float* b_hh  = (const float*)d_in[17];
    float* out = (float*)d_out;

    k_proj  <<<B * L1 + B * L2, 128>>>(x, y, Wup_w, Wup_b, Wq_w, Wq_b, Wvp_b);
    k_prep  <<<32, 512>>>(W_hh);
    k_scores<<<dim3(L2 / 32, L1 / 32, B), dim3(32, 8)>>>(xmask, ymask, V_w, V_b);
    k_softmax<<<B * L1, 128>>>();
    k_ctx   <<<dim3(L1 / 16, B), 256>>>(y);
    k_gate  <<<(B * L1) / 32, 256>>>(x, Wg_w, Wg_b);
    k_gatesx<<<dim3((B * L1) / 32, 2), 256>>>(W_ih, b_ih, b_hh);
    k_lstm  <<<B, 512>>>(out);
}